// round 14
// baseline (speedup 1.0000x reference)
#include <cuda_runtime.h>
#include <cstdint>
#include <cstddef>

// Reverse LSTM: B=128, T=2048, H=512.  out[b,t,:] = h_t (consumes x[b, T-1-t]).
//
// R12: dual-chain latency hiding. 128 CTAs = 2 pairs x 64 col-groups; each CTA
// owns 32 z-cols (8 h-cols x 4 gates, Wh slice 64KB SMEM) and interleaves TWO
// independent batch-group chains (bgA = 2p, bgB = 2p+1, 32 rows each). Each
// chain's exchange round-trip (release -> poll -> 64KB TMA) is issued at the
// end of its phase and completes during the other chain's phase, removing the
// ~10k-cycle exposed step-boundary latency that bound R2-R11 at ~20ms.

#define TT   2048
#define HID  512
#define FPAD 32              // flag padding (uints) -> 128B per flag
#define ZPAD 36              // z2 row pad: gate reads bank-conflict-free, even

__device__ float    g_Hbuf[4][2][HID * 32];    // [bg][parity][k*32 + b] k-major
__device__ unsigned g_flag[4][64][FPAD];       // [bg][cg6][0], padded

typedef unsigned long long u64;

__device__ __forceinline__ void ffma2(u64 &d, u64 a, u64 b) {
    asm volatile("fma.rn.f32x2 %0, %1, %2, %0;" : "+l"(d) : "l"(a), "l"(b));
}
__device__ __forceinline__ u64 pack2(float x) {
    u64 r; asm("mov.b64 %0, {%1, %1};" : "=l"(r) : "f"(x)); return r;
}
__device__ __forceinline__ void poll_flag(const unsigned* f, unsigned tgt) {
    unsigned v;
    do {
        asm volatile("ld.acquire.gpu.global.u32 %0, [%1];"
                     : "=r"(v) : "l"(f) : "memory");
    } while (v < tgt);
}
__device__ __forceinline__ void bulk_g2s(unsigned dst_smem, const void* src,
                                         unsigned bytes, unsigned mbar) {
    asm volatile(
        "cp.async.bulk.shared::cluster.global.mbarrier::complete_tx::bytes "
        "[%0], [%1], %2, [%3];"
        :: "r"(dst_smem), "l"(src), "r"(bytes), "r"(mbar) : "memory");
}
__device__ __forceinline__ void mbar_init(unsigned mbar, unsigned cnt) {
    asm volatile("mbarrier.init.shared.b64 [%0], %1;" :: "r"(mbar), "r"(cnt) : "memory");
}
__device__ __forceinline__ void mbar_expect_tx(unsigned mbar, unsigned bytes) {
    asm volatile("mbarrier.arrive.expect_tx.shared.b64 _, [%0], %1;"
                 :: "r"(mbar), "r"(bytes) : "memory");
}
__device__ __forceinline__ void mbar_wait(unsigned mbar, unsigned parity) {
    unsigned done;
    asm volatile(
        "{\n\t.reg .pred p;\n\t"
        "mbarrier.try_wait.parity.acquire.cta.shared::cta.b64 p, [%1], %2;\n\t"
        "selp.b32 %0, 1, 0, p;\n\t}"
        : "=r"(done) : "r"(mbar), "r"(parity) : "memory");
    if (!done) {
        asm volatile(
            "{\n\t.reg .pred P1;\n\t"
            "WL_%=:\n\t"
            "mbarrier.try_wait.parity.acquire.cta.shared::cta.b64 P1, [%0], %1, 0x989680;\n\t"
            "@P1 bra.uni WD_%=;\n\t"
            "bra.uni WL_%=;\n\t"
            "WD_%=:\n\t}"
            :: "r"(mbar), "r"(parity) : "memory");
    }
}

__global__ void lstm_init_kernel() {
    int i = threadIdx.x;                // 256 = 4*64 flags
    g_flag[i >> 6][i & 63][0] = 0u;
}

extern __shared__ float sm[];

__global__ void __launch_bounds__(256, 1)
lstm_persistent_kernel(const float* __restrict__ x,
                       const float* __restrict__ Wi,
                       const float* __restrict__ Wh,
                       const float* __restrict__ bias,
                       float* __restrict__ out)
{
    // SMEM (floats):
    //  Wh_s [k=512][c=32]   @ 0       (65536 B)   c = g*8 + jj
    //  hA_s [k=512][b=32]   @ 16384   (65536 B)
    //  hB_s [k=512][b=32]   @ 32768   (65536 B)
    //  z2   [kh=2][c=32][ZPAD] @ 49152 (9216 B)
    //  xA[32], xB[32]       @ 51456
    //  mbar u64 x2          @ 51520   (16B aligned)   total 206,096 B
    float* Wh_s = sm;
    float* hA_s = sm + 16384;
    float* hB_s = sm + 32768;
    float* z2   = sm + 49152;
    float* xA_s = sm + 51456;
    float* xB_s = sm + 51488;

    const int tid = threadIdx.x;
    const int p   = blockIdx.x >> 6;     // pair 0..1
    const int cg6 = blockIdx.x & 63;     // 0..63 -> h-cols cg6*8..cg6*8+7
    const int bgA = p * 2;
    const int bgB = p * 2 + 1;

    const int wid  = tid >> 5;           // 0..7
    const int kh   = wid >> 2;           // k-half
    const int oct  = wid & 3;            // batch octet
    const int lane = tid & 31;
    const int c2   = lane & 15;          // col pair (cols 2c2, 2c2+1)
    const int bh   = lane >> 4;          // batch nibble within octet

    const int j = tid & 7;               // gate-phase h-col
    const int b = tid >> 3;              // gate-phase batch row (0..31)

    const unsigned smem_base = (unsigned)__cvta_generic_to_shared(sm);
    const unsigned hA_smem   = smem_base + 16384u * 4u;
    const unsigned hB_smem   = smem_base + 32768u * 4u;
    const unsigned mbarA     = smem_base + 51520u * 4u;
    const unsigned mbarB     = mbarA + 8u;

    if (tid == 0) { mbar_init(mbarA, 1); mbar_init(mbarB, 1); }

    // ---- One-time: Wh slice (local c = g*8+jj <-> global g*512 + cg6*8 + jj) ----
    for (int idx = tid; idx < HID * 32; idx += 256) {
        int k = idx >> 5, c = idx & 31;
        Wh_s[idx] = Wh[(size_t)k * 2048 + (c >> 3) * 512 + cg6 * 8 + (c & 7)];
    }
    float wi_r[4], bi_r[4];
    #pragma unroll
    for (int g = 0; g < 4; ++g) {
        wi_r[g] = Wi[g * 512 + cg6 * 8 + j];
        bi_r[g] = bias[g * 512 + cg6 * 8 + j];
    }
    __syncthreads();

    float cstA = 0.f, cstB = 0.f;        // cell state for (b, j) per chain
    const size_t TH = (size_t)TT * HID;

    const int hoff = kh * 8192 + oct * 8 + bh * 4;   // into h buffers
    const int woff = kh * 8192 + c2 * 2;             // into Wh_s

    // One phase of one chain. Exchange (release -> poll -> TMA issue) happens
    // at the tail; the transfer completes during the OTHER chain's phase.
    #define PHASE(HBUF, HSMEM, BG, MBAR, XS, CST)                               \
    do {                                                                        \
        if (t > 0) mbar_wait(MBAR, (unsigned)((t - 1) & 1));                    \
        u64 a00 = 0, a01 = 0, a10 = 0, a11 = 0;                                 \
        if (t > 0) {                                                            \
            const float* hq = HBUF + hoff;                                      \
            const float* wq = Wh_s + woff;                                      \
            _Pragma("unroll 8")                                                 \
            for (int kk = 0; kk < 256; ++kk) {                                  \
                ulonglong2 hv = *(const ulonglong2*)(hq + kk * 32);             \
                float2 w = *(const float2*)(wq + kk * 32);                      \
                u64 W0 = pack2(w.x), W1 = pack2(w.y);                           \
                ffma2(a00, hv.x, W0); ffma2(a01, hv.y, W0);                     \
                ffma2(a10, hv.x, W1); ffma2(a11, hv.y, W1);                     \
            }                                                                   \
        }                                                                       \
        {                                                                       \
            float* zp = z2 + (kh * 32 + 2 * c2) * ZPAD + oct * 8 + bh * 4;      \
            *(u64*)zp = a00; *(u64*)(zp + 2) = a01;                             \
            float* zq = zp + ZPAD;                                              \
            *(u64*)zq = a10; *(u64*)(zq + 2) = a11;                             \
        }                                                                       \
        __syncthreads();                                                        \
        {                                                                       \
            float zs[4];                                                        \
            _Pragma("unroll")                                                   \
            for (int g = 0; g < 4; ++g) {                                       \
                int c = g * 8 + j;                                              \
                zs[g] = z2[c * ZPAD + b] + z2[(32 + c) * ZPAD + b];             \
            }                                                                   \
            float xr = XS[b];                                                   \
            float vi = zs[0] + xr * wi_r[0] + bi_r[0];                          \
            float vf = zs[1] + xr * wi_r[1] + bi_r[1];                          \
            float vg = zs[2] + xr * wi_r[2] + bi_r[2];                          \
            float vo = zs[3] + xr * wi_r[3] + bi_r[3];                          \
            float ig = 1.0f / (1.0f + __expf(-vi));                             \
            float fg = 1.0f / (1.0f + __expf(-vf));                             \
            float eg = __expf(2.0f * vg);                                       \
            float gv = 1.0f - 2.0f / (eg + 1.0f);                               \
            float og = 1.0f / (1.0f + __expf(-vo));                             \
            float cn = fg * (CST) + ig * gv;                                    \
            (CST) = cn;                                                         \
            float ec = __expf(2.0f * cn);                                       \
            float hr = og * (1.0f - 2.0f / (ec + 1.0f));                        \
            out[(size_t)((BG) * 32 + b) * TH + (size_t)t * HID + cg6 * 8 + j] = hr; \
            g_Hbuf[BG][(t + 1) & 1][(cg6 * 8 + j) * 32 + b] = hr;               \
        }                                                                       \
        __syncthreads();                                                        \
        if (tid == 0)                                                           \
            asm volatile("st.release.gpu.global.u32 [%0], %1;"                  \
                         :: "l"(&g_flag[BG][cg6][0]), "r"((unsigned)(t + 1))    \
                         : "memory");                                           \
        if (t < TT - 1) {                                                       \
            if (tid < 32) {                                                     \
                poll_flag(&g_flag[BG][tid][0],      (unsigned)(t + 1));         \
                poll_flag(&g_flag[BG][tid + 32][0], (unsigned)(t + 1));         \
                __syncwarp();                                                   \
                if (tid == 0) {                                                 \
                    const float* src = &g_Hbuf[BG][(t + 1) & 1][0];             \
                    mbar_expect_tx(MBAR, 65536u);                               \
                    bulk_g2s(HSMEM,          src,        32768u, MBAR);         \
                    bulk_g2s(HSMEM + 32768u, src + 8192, 32768u, MBAR);         \
                }                                                               \
            }                                                                   \
        }                                                                       \
    } while (0)

    for (int t = 0; t < TT; ++t) {
        // x for both chains this step (visible to gates via the z2 sync)
        if (tid >= 64 && tid < 96)
            xA_s[tid - 64] = x[(size_t)(bgA * 32 + (tid - 64)) * TT + (TT - 1 - t)];
        else if (tid >= 96 && tid < 128)
            xB_s[tid - 96] = x[(size_t)(bgB * 32 + (tid - 96)) * TT + (TT - 1 - t)];

        PHASE(hA_s, hA_smem, bgA, mbarA, xA_s, cstA);   // A's TMA rides under B
        PHASE(hB_s, hB_smem, bgB, mbarB, xB_s, cstB);   // B's TMA rides under next A
    }
    #undef PHASE
}

extern "C" void kernel_launch(void* const* d_in, const int* in_sizes, int n_in,
                              void* d_out, int out_size)
{
    // inputs: [0]=s (unused), [1]=x (128*2048), [2]=Wi (2048), [3]=Wh (512*2048), [4]=b (2048)
    const float* x    = (const float*)d_in[1];
    const float* Wi   = (const float*)d_in[2];
    const float* Wh   = (const float*)d_in[3];
    const float* bias = (const float*)d_in[4];
    float* out = (float*)d_out;

    size_t smem = (size_t)(51520 + 4) * sizeof(float);   // 206,096 B
    cudaFuncSetAttribute(lstm_persistent_kernel,
                         cudaFuncAttributeMaxDynamicSharedMemorySize, (int)smem);

    lstm_init_kernel<<<1, 256>>>();
    lstm_persistent_kernel<<<128, 256, smem>>>(x, Wi, Wh, bias, out);
}

// round 16
// speedup vs baseline: 1.7585x; 1.7585x over previous
#include <cuda_runtime.h>
#include <cstdint>
#include <cstddef>

// Reverse LSTM: B=128, T=2048, H=512.  out[b,t,:] = h_t (consumes x[b, T-1-t]).
//
// R16: tensor cores via mma.sync.m16n8k16 (HMMA, legal at compute_103 —
// tcgen05 is rejected by this harness's PTX target). bf16x3 split:
//   z = hi(h)@hi(W) + lo(h)@hi(W) + hi(h)@lo(W)   (error ~2^-16, << 1e-3)
// Skeleton = R2's proven protocol: 128 CTAs = 4 bg x 32 cg, per-CTA flags,
// bulk-copy staging, z2 smem exchange, identical gate math.
// 256 threads = 8 warps = (k-half kh) x (n-pair np: 16 cols = 2 n-tiles).

#define TT   2048
#define FPAD 32

typedef unsigned u32;
typedef unsigned long long u64;
typedef unsigned short u16;

// h published as bf16 hi/lo images: [bg][parity][b*512 + k]
__device__ u16 g_Hhi[4][2][32 * 512];
__device__ u16 g_Hlo[4][2][32 * 512];
__device__ u32 g_flag[4][32][FPAD];

__device__ __forceinline__ u32 bf16rn(float v) {
    u32 f = __float_as_uint(v);
    return (f + 0x7FFFu + ((f >> 16) & 1u)) >> 16;
}
__device__ __forceinline__ float bf16f(u32 bits) { return __uint_as_float(bits << 16); }

__device__ __forceinline__ void poll_flag(const u32* f, u32 tgt) {
    u32 v;
    do { asm volatile("ld.acquire.gpu.global.u32 %0, [%1];" : "=r"(v) : "l"(f) : "memory"); }
    while ((int)v < (int)tgt);
}
__device__ __forceinline__ void strel(u32* p, u32 v) {
    asm volatile("st.release.gpu.global.u32 [%0], %1;" :: "l"(p), "r"(v) : "memory");
}
__device__ __forceinline__ void bulk_g2s(u32 dst, const void* src, u32 bytes, u32 mbar) {
    asm volatile(
        "cp.async.bulk.shared::cluster.global.mbarrier::complete_tx::bytes [%0], [%1], %2, [%3];"
        :: "r"(dst), "l"(src), "r"(bytes), "r"(mbar) : "memory");
}
__device__ __forceinline__ void mbar_init(u32 m, u32 c) {
    asm volatile("mbarrier.init.shared.b64 [%0], %1;" :: "r"(m), "r"(c) : "memory");
}
__device__ __forceinline__ void mbar_expect(u32 m, u32 bytes) {
    asm volatile("mbarrier.arrive.expect_tx.shared.b64 _, [%0], %1;" :: "r"(m), "r"(bytes) : "memory");
}
__device__ __forceinline__ void mbar_wait(u32 m, u32 ph) {
    u32 done;
    asm volatile(
        "{\n\t.reg .pred p;\n\t"
        "mbarrier.try_wait.parity.acquire.cta.shared::cta.b64 p, [%1], %2;\n\t"
        "selp.b32 %0, 1, 0, p;\n\t}" : "=r"(done) : "r"(m), "r"(ph) : "memory");
    if (!done) {
        asm volatile(
            "{\n\t.reg .pred P1;\n\tWL_%=:\n\t"
            "mbarrier.try_wait.parity.acquire.cta.shared::cta.b64 P1, [%0], %1, 0x989680;\n\t"
            "@P1 bra.uni WD_%=;\n\tbra.uni WL_%=;\n\tWD_%=:\n\t}"
            :: "r"(m), "r"(ph) : "memory");
    }
}

// canonical m16n8k16 row.col bf16 mma, f32 accumulate (in place)
#define MMA(dd, A, B)                                                          \
    asm volatile(                                                              \
        "mma.sync.aligned.m16n8k16.row.col.f32.bf16.bf16.f32 "                 \
        "{%0,%1,%2,%3}, {%4,%5,%6,%7}, {%8,%9}, {%0,%1,%2,%3};"                \
        : "+f"(dd[0]), "+f"(dd[1]), "+f"(dd[2]), "+f"(dd[3])                   \
        : "r"(A[0]), "r"(A[1]), "r"(A[2]), "r"(A[3]), "r"(B[0]), "r"(B[1]))

__global__ void init_flags() {
    int i = threadIdx.x;                 // 128 = 4*32
    g_flag[i >> 5][i & 31][0] = 0u;
}

// ---- SMEM byte map (padded rows: 520 bf16 = 1040 B -> conflict-free frags) ----
#define S_WHI 0u          // Whi [64 c][520] bf16  = 66,560
#define S_WLO 66560u      // Wlo                    = 66,560
#define S_HHI 133120u     // hhi [32 b][520] bf16   = 33,280
#define S_HLO 166400u     // hlo                    = 33,280
#define S_Z2  199680u     // z2  [2 kh][32 b][80] f32 = 20,480
#define S_X   220160u     // x[32] f32 = 128
#define S_MBAR 220288u    // u64
#define S_TOT 220320u

extern __shared__ unsigned char smc[];

__global__ void __launch_bounds__(256, 1)
lstm_mma_kernel(const float* __restrict__ x,
                const float* __restrict__ Wi,
                const float* __restrict__ Wh,
                const float* __restrict__ bias,
                float* __restrict__ out)
{
    const int tid  = threadIdx.x;
    const int bg   = blockIdx.x >> 5;    // 0..3
    const int cg   = blockIdx.x & 31;    // h-cols cg*16..cg*16+15
    const int wid  = tid >> 5;           // 0..7
    const int kh   = wid >> 2;           // k-half: k in [kh*256, kh*256+256)
    const int np   = wid & 3;            // n-pair: z-cols np*16..np*16+15
    const int lane = tid & 31;
    const int g    = lane >> 2;          // fragment group row
    const int tq   = lane & 3;           // fragment thread-in-group

    const int j  = tid & 15;             // gate-phase h-col
    const int b0 = tid >> 4;             // gate-phase batch (b0 and b0+16)

    const u32 smem = (u32)__cvta_generic_to_shared(smc);
    const u32 mbar = smem + S_MBAR;
    float* z2f = (float*)(smc + S_Z2);
    float* x_s = (float*)(smc + S_X);

    if (tid == 0) mbar_init(mbar, 1);

    // ---- one-time: Wh slice as bf16 hi/lo, padded rows ----
    // local col c = ggate*16 + jj  <->  global col gg*512 + cg*16 + jj
    for (int idx = tid; idx < 64 * 512; idx += 256) {
        int k = idx >> 6, c = idx & 63;
        float w = Wh[(size_t)k * 2048 + (c >> 4) * 512 + cg * 16 + (c & 15)];
        u32 hb = bf16rn(w);
        u32 lb = bf16rn(w - bf16f(hb));
        *(u16*)(smc + S_WHI + c * 1040 + k * 2) = (u16)hb;
        *(u16*)(smc + S_WLO + c * 1040 + k * 2) = (u16)lb;
    }
    float wi_r[4], bi_r[4];
    #pragma unroll
    for (int gg = 0; gg < 4; ++gg) {
        wi_r[gg] = Wi[gg * 512 + cg * 16 + j];
        bi_r[gg] = bias[gg * 512 + cg * 16 + j];
    }
    __syncthreads();

    float cst0 = 0.f, cst1 = 0.f;        // cell state for (b0, j), (b0+16, j)
    const size_t TH = (size_t)TT * 512;

    // fragment load base offsets (bytes); per-ktile advance = 32 B
    const u32 oA = (u32)(g * 1040 + kh * 512 + tq * 4);
    const u32 oB0 = (u32)((np * 16 + g) * 1040 + kh * 512 + tq * 4);
    const u32 oB1 = oB0 + 8u * 1040u;

    for (int t = 0; t < TT; ++t) {
        // x for this step (warp 1; consumed after z2 sync)
        if (tid >= 32 && tid < 64)
            x_s[tid - 32] = x[(size_t)(bg * 32 + (tid - 32)) * TT + (TT - 1 - t)];

        float d00[4] = {0,0,0,0}, d01[4] = {0,0,0,0};
        float d10[4] = {0,0,0,0}, d11[4] = {0,0,0,0};

        if (t > 0) {
            // ---- acquire producers, stage hi/lo images (64 x 1KB row copies) ----
            if (tid < 32) {
                poll_flag(&g_flag[bg][tid][0], (u32)t);
                __syncwarp();
                if (tid == 0) mbar_expect(mbar, 65536u);
                __syncwarp();
                int rb = (lane & 15) * 2;
                const u16* srcb = (lane < 16) ? &g_Hhi[bg][t & 1][0] : &g_Hlo[bg][t & 1][0];
                u32 dstb = (lane < 16) ? S_HHI : S_HLO;
                bulk_g2s(smem + dstb + (u32)rb * 1040u,       srcb + rb * 512,       1024u, mbar);
                bulk_g2s(smem + dstb + (u32)(rb + 1) * 1040u, srcb + (rb + 1) * 512, 1024u, mbar);
            }
            mbar_wait(mbar, (u32)((t - 1) & 1));

            // ---- MMA: 16 k-tiles x (2m x 2n) x 3 passes ----
            #pragma unroll
            for (int kt = 0; kt < 16; ++kt) {
                const u32 ko = (u32)kt * 32u;
                u32 Ah0[4], Ah1[4], Al0[4], Al1[4];
                Ah0[0] = *(const u32*)(smc + S_HHI + oA + ko);
                Ah0[1] = *(const u32*)(smc + S_HHI + oA + 8u * 1040u + ko);
                Ah0[2] = *(const u32*)(smc + S_HHI + oA + ko + 16u);
                Ah0[3] = *(const u32*)(smc + S_HHI + oA + 8u * 1040u + ko + 16u);
                Ah1[0] = *(const u32*)(smc + S_HHI + oA + 16u * 1040u + ko);
                Ah1[1] = *(const u32*)(smc + S_HHI + oA + 24u * 1040u + ko);
                Ah1[2] = *(const u32*)(smc + S_HHI + oA + 16u * 1040u + ko + 16u);
                Ah1[3] = *(const u32*)(smc + S_HHI + oA + 24u * 1040u + ko + 16u);
                Al0[0] = *(const u32*)(smc + S_HLO + oA + ko);
                Al0[1] = *(const u32*)(smc + S_HLO + oA + 8u * 1040u + ko);
                Al0[2] = *(const u32*)(smc + S_HLO + oA + ko + 16u);
                Al0[3] = *(const u32*)(smc + S_HLO + oA + 8u * 1040u + ko + 16u);
                Al1[0] = *(const u32*)(smc + S_HLO + oA + 16u * 1040u + ko);
                Al1[1] = *(const u32*)(smc + S_HLO + oA + 24u * 1040u + ko);
                Al1[2] = *(const u32*)(smc + S_HLO + oA + 16u * 1040u + ko + 16u);
                Al1[3] = *(const u32*)(smc + S_HLO + oA + 24u * 1040u + ko + 16u);
                u32 Bh0[2], Bh1[2], Bl0[2], Bl1[2];
                Bh0[0] = *(const u32*)(smc + S_WHI + oB0 + ko);
                Bh0[1] = *(const u32*)(smc + S_WHI + oB0 + ko + 16u);
                Bh1[0] = *(const u32*)(smc + S_WHI + oB1 + ko);
                Bh1[1] = *(const u32*)(smc + S_WHI + oB1 + ko + 16u);
                Bl0[0] = *(const u32*)(smc + S_WLO + oB0 + ko);
                Bl0[1] = *(const u32*)(smc + S_WLO + oB0 + ko + 16u);
                Bl1[0] = *(const u32*)(smc + S_WLO + oB1 + ko);
                Bl1[1] = *(const u32*)(smc + S_WLO + oB1 + ko + 16u);

                MMA(d00, Ah0, Bh0); MMA(d00, Al0, Bh0); MMA(d00, Ah0, Bl0);
                MMA(d01, Ah0, Bh1); MMA(d01, Al0, Bh1); MMA(d01, Ah0, Bl1);
                MMA(d10, Ah1, Bh0); MMA(d10, Al1, Bh0); MMA(d10, Ah1, Bl0);
                MMA(d11, Ah1, Bh1); MMA(d11, Al1, Bh1); MMA(d11, Ah1, Bl1);
            }
        }

        // ---- scatter D frags to z2[kh][b][c] (row stride 80 floats) ----
        {
            int cA = np * 16 + 2 * tq;          // nt=0 cols
            int cB = cA + 8;                    // nt=1 cols
            float* zb = z2f + (kh * 32) * 80;
            *(float2*)&zb[(g)      * 80 + cA] = make_float2(d00[0], d00[1]);
            *(float2*)&zb[(g + 8)  * 80 + cA] = make_float2(d00[2], d00[3]);
            *(float2*)&zb[(g)      * 80 + cB] = make_float2(d01[0], d01[1]);
            *(float2*)&zb[(g + 8)  * 80 + cB] = make_float2(d01[2], d01[3]);
            *(float2*)&zb[(g + 16) * 80 + cA] = make_float2(d10[0], d10[1]);
            *(float2*)&zb[(g + 24) * 80 + cA] = make_float2(d10[2], d10[3]);
            *(float2*)&zb[(g + 16) * 80 + cB] = make_float2(d11[0], d11[1]);
            *(float2*)&zb[(g + 24) * 80 + cB] = make_float2(d11[2], d11[3]);
        }
        __syncthreads();

        // ---- gates: fold kh halves, 2 outputs per thread (b0, b0+16) ----
        {
            u16* imh = &g_Hhi[bg][(t + 1) & 1][0];
            u16* iml = &g_Hlo[bg][(t + 1) & 1][0];
            int col = cg * 16 + j;
            #pragma unroll
            for (int r = 0; r < 2; ++r) {
                int b = b0 + r * 16;
                float zg_[4];
                #pragma unroll
                for (int gg = 0; gg < 4; ++gg) {
                    int c = gg * 16 + j;
                    zg_[gg] = z2f[b * 80 + c] + z2f[(32 + b) * 80 + c];
                }
                float xr = x_s[b];
                float vi = zg_[0] + xr * wi_r[0] + bi_r[0];
                float vf = zg_[1] + xr * wi_r[1] + bi_r[1];
                float vg = zg_[2] + xr * wi_r[2] + bi_r[2];
                float vo = zg_[3] + xr * wi_r[3] + bi_r[3];
                float ig = 1.0f / (1.0f + __expf(-vi));
                float fg = 1.0f / (1.0f + __expf(-vf));
                float eg = __expf(2.0f * vg);
                float gv = 1.0f - 2.0f / (eg + 1.0f);          // tanh
                float og = 1.0f / (1.0f + __expf(-vo));
                float cp = r ? cst1 : cst0;
                float cn = fg * cp + ig * gv;
                if (r) cst1 = cn; else cst0 = cn;
                float ec = __expf(2.0f * cn);
                float hr = og * (1.0f - 2.0f / (ec + 1.0f));   // o * tanh(c)

                out[(size_t)(bg * 32 + b) * TH + (size_t)t * 512 + col] = hr;
                u32 hb = bf16rn(hr);
                u32 lb = bf16rn(hr - bf16f(hb));
                imh[b * 512 + col] = (u16)hb;
                iml[b * 512 + col] = (u16)lb;
            }
        }
        __syncthreads();
        if (tid == 0) strel(&g_flag[bg][cg][0], (u32)(t + 1));
    }
}

extern "C" void kernel_launch(void* const* d_in, const int* in_sizes, int n_in,
                              void* d_out, int out_size)
{
    // inputs: [0]=s (unused), [1]=x (128*2048), [2]=Wi (2048), [3]=Wh (512*2048), [4]=b (2048)
    const float* x    = (const float*)d_in[1];
    const float* Wi   = (const float*)d_in[2];
    const float* Wh   = (const float*)d_in[3];
    const float* bias = (const float*)d_in[4];
    float* out = (float*)d_out;

    cudaFuncSetAttribute(lstm_mma_kernel,
                         cudaFuncAttributeMaxDynamicSharedMemorySize, (int)S_TOT);

    init_flags<<<1, 128>>>();
    lstm_mma_kernel<<<128, 256, S_TOT>>>(x, Wi, Wh, bias, out);
}

// round 17
// speedup vs baseline: 1.7798x; 1.0121x over previous
#include <cuda_runtime.h>
#include <cstdint>
#include <cstddef>

// Reverse LSTM: B=128, T=2048, H=512.  out[b,t,:] = h_t (consumes x[b, T-1-t]).
//
// R17: dual-chain HMMA + dedicated comm warp (warp specialization).
// 128 CTAs = 2 pairs x 64 col-groups; CTA owns 32 z-cols (8 h-cols x 4 gates)
// and serves TWO batch-group chains (bgA=2p, bgB=2p+1, 32 rows each).
// Warp 8 (comm) polls producer flags + issues TMA staging for both chains;
// 8 compute warps (kh x np) run mma.sync bf16x3 GEMM + gates, synced by
// named barrier 1 (comm warp excluded). Each chain's exchange round-trip
// hides under the other chain's compute phase.

#define TT   2048
#define FPAD 32

typedef unsigned u32;
typedef unsigned long long u64;
typedef unsigned short u16;

// h bf16 hi/lo images: [bg][parity][b*512 + k]
__device__ u16 g_Hhi[4][2][32 * 512];
__device__ u16 g_Hlo[4][2][32 * 512];
__device__ u32 g_flag[4][64][FPAD];

__device__ __forceinline__ u32 bf16rn(float v) {
    u32 f = __float_as_uint(v);
    return (f + 0x7FFFu + ((f >> 16) & 1u)) >> 16;
}
__device__ __forceinline__ float bf16f(u32 bits) { return __uint_as_float(bits << 16); }

__device__ __forceinline__ void poll_flag(const u32* f, u32 tgt) {
    u32 v;
    do { asm volatile("ld.acquire.gpu.global.u32 %0, [%1];" : "=r"(v) : "l"(f) : "memory"); }
    while ((int)v < (int)tgt);
}
__device__ __forceinline__ void strel(u32* p, u32 v) {
    asm volatile("st.release.gpu.global.u32 [%0], %1;" :: "l"(p), "r"(v) : "memory");
}
__device__ __forceinline__ void bulk_g2s(u32 dst, const void* src, u32 bytes, u32 mbar) {
    asm volatile(
        "cp.async.bulk.shared::cluster.global.mbarrier::complete_tx::bytes [%0], [%1], %2, [%3];"
        :: "r"(dst), "l"(src), "r"(bytes), "r"(mbar) : "memory");
}
__device__ __forceinline__ void mbar_init(u32 m, u32 c) {
    asm volatile("mbarrier.init.shared.b64 [%0], %1;" :: "r"(m), "r"(c) : "memory");
}
__device__ __forceinline__ void mbar_expect(u32 m, u32 bytes) {
    asm volatile("mbarrier.arrive.expect_tx.shared.b64 _, [%0], %1;" :: "r"(m), "r"(bytes) : "memory");
}
__device__ __forceinline__ void mbar_wait(u32 m, u32 ph) {
    u32 done;
    asm volatile(
        "{\n\t.reg .pred p;\n\t"
        "mbarrier.try_wait.parity.acquire.cta.shared::cta.b64 p, [%1], %2;\n\t"
        "selp.b32 %0, 1, 0, p;\n\t}" : "=r"(done) : "r"(m), "r"(ph) : "memory");
    if (!done) {
        asm volatile(
            "{\n\t.reg .pred P1;\n\tWL_%=:\n\t"
            "mbarrier.try_wait.parity.acquire.cta.shared::cta.b64 P1, [%0], %1, 0x989680;\n\t"
            "@P1 bra.uni WD_%=;\n\tbra.uni WL_%=;\n\tWD_%=:\n\t}"
            :: "r"(m), "r"(ph) : "memory");
    }
}

// canonical m16n8k16 row.col bf16 mma, f32 accumulate (in place) — R16-proven
#define MMA(dd, A, B)                                                          \
    asm volatile(                                                              \
        "mma.sync.aligned.m16n8k16.row.col.f32.bf16.bf16.f32 "                 \
        "{%0,%1,%2,%3}, {%4,%5,%6,%7}, {%8,%9}, {%0,%1,%2,%3};"                \
        : "+f"(dd[0]), "+f"(dd[1]), "+f"(dd[2]), "+f"(dd[3])                   \
        : "r"(A[0]), "r"(A[1]), "r"(A[2]), "r"(A[3]), "r"(B[0]), "r"(B[1]))

__global__ void init_flags() {
    int i = threadIdx.x;                 // 256 = 4*64
    g_flag[i >> 6][i & 63][0] = 0u;
}

// ---- SMEM byte map (rows padded to 520 u16 = 1040 B, R16-proven layout) ----
#define S_WHI   0u        // Whi [32 c][520]      33,280
#define S_WLO   33280u    // Wlo                  33,280
#define S_AHI_A 66560u    // hA hi [32 b][520]    33,280
#define S_ALO_A 99840u    // hA lo                33,280
#define S_AHI_B 133120u   // hB hi                33,280
#define S_ALO_B 166400u   // hB lo                33,280
#define S_Z2    199680u   // z2 [2 kh][32 b][40]f 10,240
#define S_XA    209920u   // xA[32]                  128
#define S_XB    210048u   // xB[32]                  128
#define S_MBAR  210176u   // mbarA @+0, mbarB @+8     16
#define S_TOT   210208u

extern __shared__ unsigned char smc[];

__global__ void __launch_bounds__(288, 1)
lstm_mma_dual(const float* __restrict__ x,
              const float* __restrict__ Wi,
              const float* __restrict__ Wh,
              const float* __restrict__ bias,
              float* __restrict__ out)
{
    const int tid  = threadIdx.x;
    const int p    = blockIdx.x >> 6;    // pair 0..1
    const int cg   = blockIdx.x & 63;    // h-cols cg*8..cg*8+7
    const int bgA  = p * 2, bgB = p * 2 + 1;
    const int wid  = tid >> 5;           // 0..8
    const int lane = tid & 31;
    const int g    = lane >> 2;          // fragment group row
    const int tq   = lane & 3;           // fragment thread-in-group
    const int kh   = wid >> 2;           // k-half (compute warps 0..7)
    const int np   = wid & 3;            // n-octet: z-cols np*8..np*8+7

    const int j = tid & 7;               // gate-phase h-col
    const int b = tid >> 3;              // gate-phase batch (tid<256 -> 0..31)

    const u32 smem  = (u32)__cvta_generic_to_shared(smc);
    const u32 mbarA = smem + S_MBAR;
    const u32 mbarB = smem + S_MBAR + 8;
    float* z2f  = (float*)(smc + S_Z2);
    float* xA_s = (float*)(smc + S_XA);
    float* xB_s = (float*)(smc + S_XB);

    if (tid == 0) { mbar_init(mbarA, 1); mbar_init(mbarB, 1); }

    // ---- one-time: Wh slice as bf16 hi/lo (local c = gg*8+jj) ----
    for (int idx = tid; idx < 32 * 512; idx += 288) {
        int k = idx >> 5, c = idx & 31;
        float w = Wh[(size_t)k * 2048 + (c >> 3) * 512 + cg * 8 + (c & 7)];
        u32 hb = bf16rn(w);
        u32 lb = bf16rn(w - bf16f(hb));
        *(u16*)(smc + S_WHI + c * 1040 + k * 2) = (u16)hb;
        *(u16*)(smc + S_WLO + c * 1040 + k * 2) = (u16)lb;
    }
    float wi_r[4], bi_r[4];
    if (tid < 256) {
        #pragma unroll
        for (int gg = 0; gg < 4; ++gg) {
            wi_r[gg] = Wi[gg * 512 + cg * 8 + j];
            bi_r[gg] = bias[gg * 512 + cg * 8 + j];
        }
    }
    __syncthreads();

    // ================= comm warp: poll + TMA for both chains =================
    if (wid == 8) {
        for (int t = 1; t < TT; ++t) {
            poll_flag(&g_flag[bgA][lane][0],      (u32)t);
            poll_flag(&g_flag[bgA][lane + 32][0], (u32)t);
            __syncwarp();
            if (lane == 0) mbar_expect(mbarA, 65536u);
            __syncwarp();
            bulk_g2s(smem + S_AHI_A + (u32)lane * 1040u, &g_Hhi[bgA][t & 1][lane * 512], 1024u, mbarA);
            bulk_g2s(smem + S_ALO_A + (u32)lane * 1040u, &g_Hlo[bgA][t & 1][lane * 512], 1024u, mbarA);

            poll_flag(&g_flag[bgB][lane][0],      (u32)t);
            poll_flag(&g_flag[bgB][lane + 32][0], (u32)t);
            __syncwarp();
            if (lane == 0) mbar_expect(mbarB, 65536u);
            __syncwarp();
            bulk_g2s(smem + S_AHI_B + (u32)lane * 1040u, &g_Hhi[bgB][t & 1][lane * 512], 1024u, mbarB);
            bulk_g2s(smem + S_ALO_B + (u32)lane * 1040u, &g_Hlo[bgB][t & 1][lane * 512], 1024u, mbarB);
        }
        return;
    }

    // ================= compute warps (tid < 256) =================
    float cstA = 0.f, cstB = 0.f;
    const size_t TH = (size_t)TT * 512;

    const u32 oAr = (u32)(g * 1040 + kh * 512 + tq * 4);
    const u32 oBr = (u32)((np * 8 + g) * 1040 + kh * 512 + tq * 4);

    #define PHASE(SAHI, SALO, MBAR, BG, XS, CST)                                    \
    do {                                                                            \
        float d00[4] = {0,0,0,0}, d10[4] = {0,0,0,0};                               \
        if (t > 0) {                                                                \
            mbar_wait(MBAR, (u32)((t - 1) & 1));                                    \
            _Pragma("unroll")                                                       \
            for (int kt = 0; kt < 16; ++kt) {                                       \
                const u32 ko = (u32)kt * 32u;                                       \
                u32 Ah0[4], Ah1[4], Al0[4], Al1[4], Bh[2], Bl[2];                   \
                Ah0[0] = *(const u32*)(smc + SAHI + oAr + ko);                      \
                Ah0[1] = *(const u32*)(smc + SAHI + oAr + 8u*1040u + ko);           \
                Ah0[2] = *(const u32*)(smc + SAHI + oAr + ko + 16u);                \
                Ah0[3] = *(const u32*)(smc + SAHI + oAr + 8u*1040u + ko + 16u);     \
                Ah1[0] = *(const u32*)(smc + SAHI + oAr + 16u*1040u + ko);          \
                Ah1[1] = *(const u32*)(smc + SAHI + oAr + 24u*1040u + ko);          \
                Ah1[2] = *(const u32*)(smc + SAHI + oAr + 16u*1040u + ko + 16u);    \
                Ah1[3] = *(const u32*)(smc + SAHI + oAr + 24u*1040u + ko + 16u);    \
                Al0[0] = *(const u32*)(smc + SALO + oAr + ko);                      \
                Al0[1] = *(const u32*)(smc + SALO + oAr + 8u*1040u + ko);           \
                Al0[2] = *(const u32*)(smc + SALO + oAr + ko + 16u);                \
                Al0[3] = *(const u32*)(smc + SALO + oAr + 8u*1040u + ko + 16u);     \
                Al1[0] = *(const u32*)(smc + SALO + oAr + 16u*1040u + ko);          \
                Al1[1] = *(const u32*)(smc + SALO + oAr + 24u*1040u + ko);          \
                Al1[2] = *(const u32*)(smc + SALO + oAr + 16u*1040u + ko + 16u);    \
                Al1[3] = *(const u32*)(smc + SALO + oAr + 24u*1040u + ko + 16u);    \
                Bh[0] = *(const u32*)(smc + S_WHI + oBr + ko);                      \
                Bh[1] = *(const u32*)(smc + S_WHI + oBr + ko + 16u);                \
                Bl[0] = *(const u32*)(smc + S_WLO + oBr + ko);                      \
                Bl[1] = *(const u32*)(smc + S_WLO + oBr + ko + 16u);                \
                MMA(d00, Ah0, Bh); MMA(d00, Al0, Bh); MMA(d00, Ah0, Bl);            \
                MMA(d10, Ah1, Bh); MMA(d10, Al1, Bh); MMA(d10, Ah1, Bl);            \
            }                                                                       \
        }                                                                           \
        {                                                                           \
            int cA = np * 8 + 2 * tq;                                               \
            float* zb = z2f + kh * 32 * 40;                                         \
            *(float2*)&zb[(g)      * 40 + cA] = make_float2(d00[0], d00[1]);        \
            *(float2*)&zb[(g + 8)  * 40 + cA] = make_float2(d00[2], d00[3]);        \
            *(float2*)&zb[(g + 16) * 40 + cA] = make_float2(d10[0], d10[1]);        \
            *(float2*)&zb[(g + 24) * 40 + cA] = make_float2(d10[2], d10[3]);        \
        }                                                                           \
        asm volatile("bar.sync 1, 256;" ::: "memory");                              \
        {                                                                           \
            float zg_[4];                                                           \
            _Pragma("unroll")                                                       \
            for (int gg = 0; gg < 4; ++gg) {                                        \
                int c = gg * 8 + j;                                                 \
                zg_[gg] = z2f[b * 40 + c] + z2f[(32 + b) * 40 + c];                 \
            }                                                                       \
            float xr = XS[b];                                                       \
            float vi = zg_[0] + xr * wi_r[0] + bi_r[0];                             \
            float vf = zg_[1] + xr * wi_r[1] + bi_r[1];                             \
            float vg = zg_[2] + xr * wi_r[2] + bi_r[2];                             \
            float vo = zg_[3] + xr * wi_r[3] + bi_r[3];                             \
            float ig = 1.0f / (1.0f + __expf(-vi));                                 \
            float fg = 1.0f / (1.0f + __expf(-vf));                                 \
            float eg = __expf(2.0f * vg);                                           \
            float gv = 1.0f - 2.0f / (eg + 1.0f);                                   \
            float og = 1.0f / (1.0f + __expf(-vo));                                 \
            float cn = fg * (CST) + ig * gv;                                        \
            (CST) = cn;                                                             \
            float ec = __expf(2.0f * cn);                                           \
            float hr = og * (1.0f - 2.0f / (ec + 1.0f));                            \
            out[(size_t)((BG) * 32 + b) * TH + (size_t)t * 512 + cg * 8 + j] = hr;  \
            u32 hb = bf16rn(hr);                                                    \
            u32 lb = bf16rn(hr - bf16f(hb));                                        \
            g_Hhi[BG][(t + 1) & 1][b * 512 + cg * 8 + j] = (u16)hb;                 \
            g_Hlo[BG][(t + 1) & 1][b * 512 + cg * 8 + j] = (u16)lb;                 \
        }                                                                           \
        asm volatile("bar.sync 1, 256;" ::: "memory");                              \
        if (tid == 0) strel(&g_flag[BG][cg][0], (u32)(t + 1));                      \
    } while (0)

    for (int t = 0; t < TT; ++t) {
        // x for both chains (ordered before gate reads by the phase barriers)
        if (tid >= 64 && tid < 96)
            xA_s[tid - 64] = x[(size_t)(bgA * 32 + (tid - 64)) * TT + (TT - 1 - t)];
        else if (tid >= 96 && tid < 128)
            xB_s[tid - 96] = x[(size_t)(bgB * 32 + (tid - 96)) * TT + (TT - 1 - t)];

        PHASE(S_AHI_A, S_ALO_A, mbarA, bgA, xA_s, cstA);  // A exchange hides under B
        PHASE(S_AHI_B, S_ALO_B, mbarB, bgB, xB_s, cstB);  // B exchange hides under next A
    }
    #undef PHASE
}

extern "C" void kernel_launch(void* const* d_in, const int* in_sizes, int n_in,
                              void* d_out, int out_size)
{
    // inputs: [0]=s (unused), [1]=x (128*2048), [2]=Wi (2048), [3]=Wh (512*2048), [4]=b (2048)
    const float* x    = (const float*)d_in[1];
    const float* Wi   = (const float*)d_in[2];
    const float* Wh   = (const float*)d_in[3];
    const float* bias = (const float*)d_in[4];
    float* out = (float*)d_out;

    cudaFuncSetAttribute(lstm_mma_dual,
                         cudaFuncAttributeMaxDynamicSharedMemorySize, (int)S_TOT);

    init_flags<<<1, 256>>>();
    lstm_mma_dual<<<128, 288, S_TOT>>>(x, Wi, Wh, bias, out);
}